// round 9
// baseline (speedup 1.0000x reference)
#include <cuda_runtime.h>
#include <cuda_bf16.h>

// Problem constants (fixed by the reference: B=16,S=16 -> BS=256)
#define L_TOK   128          // tokens per sentence
#define NARG    8            // A
#define NTOK    8            // T
#define EMB_D   768          // D
#define D4      (EMB_D / 4)  // 192 float4 per full row
#define D4H     (D4 / 2)     // 96 float4 groups owned per CTA
#define NP      24           // 3 arg-sets * NARG
#define HALF_P  12           // p split inside sparse sub-group
#define BDIM    384          // 192 mean + 192 sparse threads

// flat entry: l (bits 0..6) | w (bits 7..10) | p (bits 11..15)
struct SmemLayout {
    int            s_ids[L_TOK];
    float          s_m[L_TOK];
    int            s_arg[NP * NTOK];
    unsigned char  wtab[NP * L_TOK];     // 3 KB  per (p,l) match weight
    int            cnt[NP];              // entries per p
    int            cursor[NP];           // placement cursors
    int            offs[NP + 1];         // exclusive scan of cnt
    unsigned short flat[NP * L_TOK];     // 6 KB  events sorted by p
    int            s_tot[NP];            // total matched tokens per p
    float          s_inv[NP];            // 1/tot or 0
    float4         pmean[D4H];           // 1.5 KB  token-half-1 partial sums
    float          ms_hi;                // token-half-1 mask sum
};

#define BAR_MEAN()   asm volatile("bar.sync 1, 192;" ::: "memory")
#define BAR_SPARSE() asm volatile("bar.sync 2, 192;" ::: "memory")

__global__ void __launch_bounds__(BDIM)
slmuse_fused_kernel(const int*   __restrict__ sent_ids,
                    const int*   __restrict__ att_mask,
                    const int*   __restrict__ pred_ids,
                    const int*   __restrict__ arg0_ids,
                    const int*   __restrict__ arg1_ids,
                    const float* __restrict__ emb,
                    float*       __restrict__ out,
                    int BS)
{
    __shared__ SmemLayout sm;

    const int tid   = threadIdx.x;
    const int bs    = blockIdx.x >> 1;        // sentence pair
    const int chalf = blockIdx.x & 1;         // column half 0/1

    float* out_mean = out;                               // [BS, D]
    float* out_sets = out + (size_t)BS * EMB_D;          // 3 x [BS, A, D]
    const size_t set_stride = (size_t)BS * NARG * EMB_D;

    // ---- Phase 1: stage ids / mask / arg ids (all threads), one sync ----
    if (tid < L_TOK) {
        sm.s_ids[tid] = sent_ids[(size_t)bs * L_TOK + tid];
        sm.s_m[tid]   = (float)att_mask[(size_t)bs * L_TOK + tid];
    }
    if (tid < NP * NTOK) {                 // 192 elements
        int p = tid / NTOK, t = tid % NTOK;
        int set = p / NARG, a = p % NARG;
        const int* src = (set == 0) ? pred_ids : (set == 1) ? arg0_ids : arg1_ids;
        sm.s_arg[tid] = src[((size_t)bs * NARG + a) * NTOK + t];
    }
    if (tid < NP) { sm.cnt[tid] = 0; sm.s_tot[tid] = 0; }
    __syncthreads();   // the ONLY full-block barrier

    if (tid < 192) {
        // ======= MEAN SUB-GROUP: 2 threads/column, token halves ============
        const int cloc  = tid % D4H;               // 0..95 local column group
        const int thalf = tid / D4H;               // 0 or 1 (token half)
        const int cgrp  = chalf * D4H + cloc;      // global float4 column
        const float4* cb = reinterpret_cast<const float4*>(
                               emb + (size_t)bs * L_TOK * EMB_D) + cgrp;
        const int l_beg = thalf * (L_TOK / 2);     // 0 or 64

        float4 a0 = {0,0,0,0}, a1 = {0,0,0,0}, a2 = {0,0,0,0}, a3 = {0,0,0,0};
        float4 a4 = {0,0,0,0}, a5 = {0,0,0,0}, a6 = {0,0,0,0}, a7 = {0,0,0,0};
        float  ms = 0.f;
        #pragma unroll 2
        for (int l = l_beg; l < l_beg + L_TOK / 2; l += 8) {
            float4 v0 = cb[(l + 0) * D4];
            float4 v1 = cb[(l + 1) * D4];
            float4 v2 = cb[(l + 2) * D4];
            float4 v3 = cb[(l + 3) * D4];
            float4 v4 = cb[(l + 4) * D4];
            float4 v5 = cb[(l + 5) * D4];
            float4 v6 = cb[(l + 6) * D4];
            float4 v7 = cb[(l + 7) * D4];
            float m0 = sm.s_m[l + 0], m1 = sm.s_m[l + 1];
            float m2 = sm.s_m[l + 2], m3 = sm.s_m[l + 3];
            float m4 = sm.s_m[l + 4], m5 = sm.s_m[l + 5];
            float m6 = sm.s_m[l + 6], m7 = sm.s_m[l + 7];
            ms += ((m0 + m1) + (m2 + m3)) + ((m4 + m5) + (m6 + m7));
            a0.x += m0*v0.x; a0.y += m0*v0.y; a0.z += m0*v0.z; a0.w += m0*v0.w;
            a1.x += m1*v1.x; a1.y += m1*v1.y; a1.z += m1*v1.z; a1.w += m1*v1.w;
            a2.x += m2*v2.x; a2.y += m2*v2.y; a2.z += m2*v2.z; a2.w += m2*v2.w;
            a3.x += m3*v3.x; a3.y += m3*v3.y; a3.z += m3*v3.z; a3.w += m3*v3.w;
            a4.x += m4*v4.x; a4.y += m4*v4.y; a4.z += m4*v4.z; a4.w += m4*v4.w;
            a5.x += m5*v5.x; a5.y += m5*v5.y; a5.z += m5*v5.z; a5.w += m5*v5.w;
            a6.x += m6*v6.x; a6.y += m6*v6.y; a6.z += m6*v6.z; a6.w += m6*v6.w;
            a7.x += m7*v7.x; a7.y += m7*v7.y; a7.z += m7*v7.z; a7.w += m7*v7.w;
        }
        float4 part;
        part.x = ((a0.x+a1.x)+(a2.x+a3.x))+((a4.x+a5.x)+(a6.x+a7.x));
        part.y = ((a0.y+a1.y)+(a2.y+a3.y))+((a4.y+a5.y)+(a6.y+a7.y));
        part.z = ((a0.z+a1.z)+(a2.z+a3.z))+((a4.z+a5.z)+(a6.z+a7.z));
        part.w = ((a0.w+a1.w)+(a2.w+a3.w))+((a4.w+a5.w)+(a6.w+a7.w));

        if (thalf == 1) {
            sm.pmean[cloc] = part;
            if (cloc == 0) sm.ms_hi = ms;
            BAR_MEAN();
        } else {
            BAR_MEAN();
            float4 ph = sm.pmean[cloc];
            float minv = 1.f / fmaxf(ms + sm.ms_hi, 1.f);
            float4 r;
            r.x = (part.x + ph.x) * minv;
            r.y = (part.y + ph.y) * minv;
            r.z = (part.z + ph.z) * minv;
            r.w = (part.w + ph.w) * minv;
            *reinterpret_cast<float4*>(
                out_mean + (size_t)bs * EMB_D + 4 * cgrp) = r;
        }
    } else {
        // ======= SPARSE SUB-GROUP: build (hidden), then 2 thr/col p-split ==
        const int stid = tid - 192;                // 0..191

        // Build 2a: match weights + per-p counts (16 iterations)
        for (int task = stid; task < NP * L_TOK; task += 192) {
            int p = task >> 7;
            int l = task & (L_TOK - 1);
            int sid = sm.s_ids[l];
            int w = 0;
            #pragma unroll
            for (int t = 0; t < NTOK; t++) {
                int aid = sm.s_arg[p * NTOK + t];
                w += (aid != 0 && aid == sid) ? 1 : 0;
            }
            sm.wtab[task] = (unsigned char)w;
            if (w) {
                atomicAdd(&sm.cnt[p], 1);
                atomicAdd(&sm.s_tot[p], w);
            }
        }
        BAR_SPARSE();

        // Build 2b: exclusive scan (1 thread)
        if (stid == 0) {
            int run = 0;
            #pragma unroll
            for (int p = 0; p < NP; p++) { sm.offs[p] = run; run += sm.cnt[p]; }
            sm.offs[NP] = run;
        }
        BAR_SPARSE();
        if (stid < NP) {
            sm.cursor[stid] = sm.offs[stid];
            int tot = sm.s_tot[stid];
            sm.s_inv[stid] = (tot > 0) ? (1.f / (float)tot) : 0.f;
        }
        BAR_SPARSE();

        // Build 2c: place events into p-sorted flat list
        for (int task = stid; task < NP * L_TOK; task += 192) {
            int w = sm.wtab[task];
            if (w) {
                int p = task >> 7;
                int l = task & (L_TOK - 1);
                int pos = atomicAdd(&sm.cursor[p], 1);
                sm.flat[pos] = (unsigned short)(l | (w << 7) | (p << 11));
            }
        }
        BAR_SPARSE();

        // Walk: 2 threads per column, p-range halves
        const int cloc = stid % D4H;               // 0..95 local column group
        const int prng = stid / D4H;               // 0 or 1
        const int cgrp = chalf * D4H + cloc;
        const float4* cb = reinterpret_cast<const float4*>(
                               emb + (size_t)bs * L_TOK * EMB_D) + cgrp;
        const int ocol = 4 * cgrp;

        const int p_beg = prng * HALF_P;
        const int p_end = p_beg + HALF_P;
        const int j_beg = sm.offs[p_beg];
        const int j_end = sm.offs[p_end];

        float4 acc = {0,0,0,0};
        int curp = p_beg;

        for (int j0 = j_beg; j0 < j_end; j0 += 8) {
            float4 vals[8];
            int    es[8];
            #pragma unroll
            for (int k = 0; k < 8; k++) {
                int j = j0 + k;
                int e = (j < j_end) ? (int)sm.flat[j] : (p_end << 11); // sentinel
                es[k] = e;
                if (j < j_end) vals[k] = cb[(e & 127) * D4];
                else           vals[k] = make_float4(0.f, 0.f, 0.f, 0.f);
            }
            #pragma unroll
            for (int k = 0; k < 8; k++) {
                int p = es[k] >> 11;
                if (p != curp) {                       // uniform across sub-half
                    for (int q = curp; q < p && q < p_end; q++) {
                        float s = (q == curp) ? sm.s_inv[q] : 0.f;
                        float4 r;
                        r.x = acc.x * s; r.y = acc.y * s;
                        r.z = acc.z * s; r.w = acc.w * s;
                        int set = q >> 3, a = q & 7;
                        *reinterpret_cast<float4*>(
                            out_sets + (size_t)set * set_stride
                            + ((size_t)bs * NARG + a) * EMB_D + ocol) = r;
                    }
                    curp = p;
                    acc = make_float4(0.f, 0.f, 0.f, 0.f);
                }
                float w = (float)((es[k] >> 7) & 15);
                acc.x += w * vals[k].x; acc.y += w * vals[k].y;
                acc.z += w * vals[k].z; acc.w += w * vals[k].w;
            }
        }
        // tail: remaining p's in range (including empty range)
        for (int q = curp; q < p_end; q++) {
            float s = (q == curp) ? sm.s_inv[q] : 0.f;
            float4 r;
            r.x = acc.x * s; r.y = acc.y * s; r.z = acc.z * s; r.w = acc.w * s;
            int set = q >> 3, a = q & 7;
            *reinterpret_cast<float4*>(
                out_sets + (size_t)set * set_stride
                + ((size_t)bs * NARG + a) * EMB_D + ocol) = r;
        }
    }
}

extern "C" void kernel_launch(void* const* d_in, const int* in_sizes, int n_in,
                              void* d_out, int out_size)
{
    const int*   sent = (const int*)  d_in[0];
    const int*   mask = (const int*)  d_in[1];
    const int*   pred = (const int*)  d_in[2];
    const int*   a0   = (const int*)  d_in[3];
    const int*   a1   = (const int*)  d_in[4];
    const float* emb  = (const float*)d_in[5];
    float*       out  = (float*)      d_out;

    const int BS = in_sizes[0] / L_TOK;   // 256

    slmuse_fused_kernel<<<BS * 2, BDIM>>>(
        sent, mask, pred, a0, a1, emb, out, BS);
}

// round 10
// speedup vs baseline: 1.1238x; 1.1238x over previous
#include <cuda_runtime.h>
#include <cuda_bf16.h>

// Problem constants (fixed by the reference: B=16,S=16 -> BS=256)
#define L_TOK   128          // tokens per sentence
#define NARG    8            // A
#define NTOK    8            // T
#define EMB_D   768          // D
#define D4      (EMB_D / 4)  // 192 float4 per row
#define NP      24           // 3 arg-sets * NARG
#define BDIM    384          // 192 mean threads + 192 sparse threads

// flat entry: l (bits 0..6) | w (bits 7..10) | p (bits 11..15)
struct SmemLayout {
    int            s_ids[L_TOK];
    float          s_m[L_TOK];
    int            s_arg[NP * NTOK];
    unsigned char  wtab[NP * L_TOK];     // 3 KB  per (p,l) match weight
    int            cnt[NP];              // entries per p
    int            cursor[NP];           // placement cursors
    int            offs[NP + 1];         // exclusive scan of cnt
    unsigned short flat[NP * L_TOK];     // 6 KB  events sorted by p
    int            s_tot[NP];            // total matched tokens per p
    float          s_inv[NP];            // 1/tot or 0
};

// Sparse-half-only barrier (warps 6..11, 192 threads)
#define BAR_SPARSE() asm volatile("bar.sync 2, 192;" ::: "memory")

__global__ void __launch_bounds__(BDIM)
slmuse_fused_kernel(const int*   __restrict__ sent_ids,
                    const int*   __restrict__ att_mask,
                    const int*   __restrict__ pred_ids,
                    const int*   __restrict__ arg0_ids,
                    const int*   __restrict__ arg1_ids,
                    const float* __restrict__ emb,
                    float*       __restrict__ out,
                    int BS)
{
    __shared__ SmemLayout sm;

    const int tid  = threadIdx.x;
    const int bs   = blockIdx.x;              // one CTA per sentence pair

    float* out_mean = out;                               // [BS, D]
    float* out_sets = out + (size_t)BS * EMB_D;          // 3 x [BS, A, D]
    const size_t set_stride = (size_t)BS * NARG * EMB_D;

    // ---- Phase 1: stage ids / mask / arg ids (all threads), ONE sync ----
    if (tid < L_TOK) {
        sm.s_ids[tid] = sent_ids[(size_t)bs * L_TOK + tid];
        sm.s_m[tid]   = (float)att_mask[(size_t)bs * L_TOK + tid];
    }
    if (tid < NP * NTOK) {                 // 192 elements
        int p = tid / NTOK, t = tid % NTOK;
        int set = p / NARG, a = p % NARG;
        const int* src = (set == 0) ? pred_ids : (set == 1) ? arg0_ids : arg1_ids;
        sm.s_arg[tid] = src[((size_t)bs * NARG + a) * NTOK + t];
    }
    if (tid < NP) { sm.cnt[tid] = 0; sm.s_tot[tid] = 0; }
    __syncthreads();   // the ONLY full-block barrier

    if (tid < 192) {
        // ======== MEAN WARPS: start streaming IMMEDIATELY =================
        const int ctid = tid;
        const float4* cb = reinterpret_cast<const float4*>(
                               emb + (size_t)bs * L_TOK * EMB_D) + ctid;

        float4 a0 = {0,0,0,0}, a1 = {0,0,0,0}, a2 = {0,0,0,0}, a3 = {0,0,0,0};
        float4 a4 = {0,0,0,0}, a5 = {0,0,0,0}, a6 = {0,0,0,0}, a7 = {0,0,0,0};
        float  ms = 0.f;                       // private mask sum (no barrier)
        #pragma unroll 2
        for (int l = 0; l < L_TOK; l += 8) {
            float4 v0 = cb[(l + 0) * D4];
            float4 v1 = cb[(l + 1) * D4];
            float4 v2 = cb[(l + 2) * D4];
            float4 v3 = cb[(l + 3) * D4];
            float4 v4 = cb[(l + 4) * D4];
            float4 v5 = cb[(l + 5) * D4];
            float4 v6 = cb[(l + 6) * D4];
            float4 v7 = cb[(l + 7) * D4];
            float m0 = sm.s_m[l + 0], m1 = sm.s_m[l + 1];
            float m2 = sm.s_m[l + 2], m3 = sm.s_m[l + 3];
            float m4 = sm.s_m[l + 4], m5 = sm.s_m[l + 5];
            float m6 = sm.s_m[l + 6], m7 = sm.s_m[l + 7];
            ms += ((m0 + m1) + (m2 + m3)) + ((m4 + m5) + (m6 + m7));
            a0.x += m0*v0.x; a0.y += m0*v0.y; a0.z += m0*v0.z; a0.w += m0*v0.w;
            a1.x += m1*v1.x; a1.y += m1*v1.y; a1.z += m1*v1.z; a1.w += m1*v1.w;
            a2.x += m2*v2.x; a2.y += m2*v2.y; a2.z += m2*v2.z; a2.w += m2*v2.w;
            a3.x += m3*v3.x; a3.y += m3*v3.y; a3.z += m3*v3.z; a3.w += m3*v3.w;
            a4.x += m4*v4.x; a4.y += m4*v4.y; a4.z += m4*v4.z; a4.w += m4*v4.w;
            a5.x += m5*v5.x; a5.y += m5*v5.y; a5.z += m5*v5.z; a5.w += m5*v5.w;
            a6.x += m6*v6.x; a6.y += m6*v6.y; a6.z += m6*v6.z; a6.w += m6*v6.w;
            a7.x += m7*v7.x; a7.y += m7*v7.y; a7.z += m7*v7.z; a7.w += m7*v7.w;
        }
        float minv = 1.f / fmaxf(ms, 1.f);
        float4 r;
        r.x = (((a0.x+a1.x)+(a2.x+a3.x))+((a4.x+a5.x)+(a6.x+a7.x))) * minv;
        r.y = (((a0.y+a1.y)+(a2.y+a3.y))+((a4.y+a5.y)+(a6.y+a7.y))) * minv;
        r.z = (((a0.z+a1.z)+(a2.z+a3.z))+((a4.z+a5.z)+(a6.z+a7.z))) * minv;
        r.w = (((a0.w+a1.w)+(a2.w+a3.w))+((a4.w+a5.w)+(a6.w+a7.w))) * minv;
        *reinterpret_cast<float4*>(out_mean + (size_t)bs * EMB_D + 4 * ctid) = r;
    } else {
        // ======== SPARSE WARPS: build list (overlapped w/ mean), then walk =
        const int stid = tid - 192;            // 0..191
        const int ctid = stid;

        // Build 2a: match weights + per-p counts (16 iterations)
        for (int task = stid; task < NP * L_TOK; task += 192) {
            int p = task >> 7;
            int l = task & (L_TOK - 1);
            int sid = sm.s_ids[l];
            int w = 0;
            #pragma unroll
            for (int t = 0; t < NTOK; t++) {
                int aid = sm.s_arg[p * NTOK + t];
                w += (aid != 0 && aid == sid) ? 1 : 0;
            }
            sm.wtab[task] = (unsigned char)w;
            if (w) {
                atomicAdd(&sm.cnt[p], 1);
                atomicAdd(&sm.s_tot[p], w);
            }
        }
        BAR_SPARSE();

        // Build 2b: exclusive scan (1 thread, 24 elems)
        if (stid == 0) {
            int run = 0;
            #pragma unroll
            for (int p = 0; p < NP; p++) { sm.offs[p] = run; run += sm.cnt[p]; }
            sm.offs[NP] = run;
        }
        BAR_SPARSE();
        if (stid < NP) {
            sm.cursor[stid] = sm.offs[stid];
            int tot = sm.s_tot[stid];
            sm.s_inv[stid] = (tot > 0) ? (1.f / (float)tot) : 0.f;
        }
        BAR_SPARSE();

        // Build 2c: place events into p-sorted flat list
        for (int task = stid; task < NP * L_TOK; task += 192) {
            int w = sm.wtab[task];
            if (w) {
                int p = task >> 7;
                int l = task & (L_TOK - 1);
                int pos = atomicAdd(&sm.cursor[p], 1);
                sm.flat[pos] = (unsigned short)(l | (w << 7) | (p << 11));
            }
        }
        BAR_SPARSE();

        // Walk: full p range, p-sorted register walk, float4, MLP=8
        const float4* cb = reinterpret_cast<const float4*>(
                               emb + (size_t)bs * L_TOK * EMB_D) + ctid;
        const int ocol = 4 * ctid;

        const int total = sm.offs[NP];
        float4 acc = {0,0,0,0};
        int curp = 0;

        for (int j0 = 0; j0 < total; j0 += 8) {
            float4 vals[8];
            int    es[8];
            #pragma unroll
            for (int k = 0; k < 8; k++) {
                int j = j0 + k;
                int e = (j < total) ? (int)sm.flat[j] : (NP << 11);  // sentinel
                es[k] = e;
                if (j < total) vals[k] = cb[(e & 127) * D4];
                else           vals[k] = make_float4(0.f, 0.f, 0.f, 0.f);
            }
            #pragma unroll
            for (int k = 0; k < 8; k++) {
                int p = es[k] >> 11;
                if (p != curp) {                       // uniform across half
                    for (int q = curp; q < p && q < NP; q++) {
                        float s = (q == curp) ? sm.s_inv[q] : 0.f;
                        float4 r;
                        r.x = acc.x * s; r.y = acc.y * s;
                        r.z = acc.z * s; r.w = acc.w * s;
                        int set = q >> 3, a = q & 7;
                        *reinterpret_cast<float4*>(
                            out_sets + (size_t)set * set_stride
                            + ((size_t)bs * NARG + a) * EMB_D + ocol) = r;
                    }
                    curp = p;
                    acc = make_float4(0.f, 0.f, 0.f, 0.f);
                }
                float w = (float)((es[k] >> 7) & 15);
                acc.x += w * vals[k].x; acc.y += w * vals[k].y;
                acc.z += w * vals[k].z; acc.w += w * vals[k].w;
            }
        }
        // tail: remaining p's (including all-empty case)
        for (int q = curp; q < NP; q++) {
            float s = (q == curp) ? sm.s_inv[q] : 0.f;
            float4 r;
            r.x = acc.x * s; r.y = acc.y * s; r.z = acc.z * s; r.w = acc.w * s;
            int set = q >> 3, a = q & 7;
            *reinterpret_cast<float4*>(
                out_sets + (size_t)set * set_stride
                + ((size_t)bs * NARG + a) * EMB_D + ocol) = r;
        }
    }
}

extern "C" void kernel_launch(void* const* d_in, const int* in_sizes, int n_in,
                              void* d_out, int out_size)
{
    const int*   sent = (const int*)  d_in[0];
    const int*   mask = (const int*)  d_in[1];
    const int*   pred = (const int*)  d_in[2];
    const int*   a0   = (const int*)  d_in[3];
    const int*   a1   = (const int*)  d_in[4];
    const float* emb  = (const float*)d_in[5];
    float*       out  = (float*)      d_out;

    const int BS = in_sizes[0] / L_TOK;   // 256

    slmuse_fused_kernel<<<BS, BDIM>>>(
        sent, mask, pred, a0, a1, emb, out, BS);
}

// round 11
// speedup vs baseline: 1.1344x; 1.0094x over previous
#include <cuda_runtime.h>
#include <cuda_bf16.h>

// Problem constants (fixed by the reference: B=16,S=16 -> BS=256)
#define L_TOK   128          // tokens per sentence
#define NARG    8            // A
#define NTOK    8            // T
#define EMB_D   768          // D
#define D4      (EMB_D / 4)  // 192 float4 per row
#define NP      24           // 3 arg-sets * NARG
#define BDIM    384          // 192 mean threads + 192 sparse threads

// flat entry: l (bits 0..6) | w (bits 7..10) | p (bits 11..15)
struct SmemLayout {
    int            s_ids[L_TOK];
    float          s_m[L_TOK];
    int            s_arg[NP * NTOK];
    unsigned char  wtab[NP * L_TOK];        // 3 KB  per (p,l) match weight
    int            cnt[NP];                 // entries per p
    int            cursor[NP];              // placement cursors
    int            offs[NP + 1];            // exclusive scan of cnt
    unsigned short flat[NP * L_TOK + 8];    // 6 KB  events sorted by p (+pad)
    int            s_tot[NP];               // total matched tokens per p
    float          s_inv[NP];               // 1/tot or 0
    int            total_pad;               // padded entry count
};

// Sparse-half-only barrier (warps 6..11, 192 threads)
#define BAR_SPARSE() asm volatile("bar.sync 2, 192;" ::: "memory")

__global__ void __launch_bounds__(BDIM, 3)
slmuse_fused_kernel(const int*   __restrict__ sent_ids,
                    const int*   __restrict__ att_mask,
                    const int*   __restrict__ pred_ids,
                    const int*   __restrict__ arg0_ids,
                    const int*   __restrict__ arg1_ids,
                    const float* __restrict__ emb,
                    float*       __restrict__ out,
                    int BS)
{
    __shared__ SmemLayout sm;

    const int tid  = threadIdx.x;
    const int bs   = blockIdx.x;              // one CTA per sentence pair

    float* out_mean = out;                               // [BS, D]
    float* out_sets = out + (size_t)BS * EMB_D;          // 3 x [BS, A, D]
    const size_t set_stride = (size_t)BS * NARG * EMB_D;

    // ---- Phase 1: stage ids / mask / arg ids (all threads), ONE sync ----
    if (tid < L_TOK) {
        sm.s_ids[tid] = sent_ids[(size_t)bs * L_TOK + tid];
        sm.s_m[tid]   = (float)att_mask[(size_t)bs * L_TOK + tid];
    }
    if (tid < NP * NTOK) {                 // 192 elements
        int p = tid / NTOK, t = tid % NTOK;
        int set = p / NARG, a = p % NARG;
        const int* src = (set == 0) ? pred_ids : (set == 1) ? arg0_ids : arg1_ids;
        sm.s_arg[tid] = src[((size_t)bs * NARG + a) * NTOK + t];
    }
    if (tid < NP) { sm.cnt[tid] = 0; sm.s_tot[tid] = 0; }
    __syncthreads();   // the ONLY full-block barrier

    if (tid < 192) {
        // ======== MEAN WARPS: stream immediately, 4-acc / 8-in-flight =====
        const int ctid = tid;
        const float4* cb = reinterpret_cast<const float4*>(
                               emb + (size_t)bs * L_TOK * EMB_D) + ctid;

        float4 a0 = {0,0,0,0}, a1 = {0,0,0,0}, a2 = {0,0,0,0}, a3 = {0,0,0,0};
        float  ms = 0.f;                       // private mask sum (no barrier)
        #pragma unroll 2
        for (int l = 0; l < L_TOK; l += 4) {
            float4 v0 = cb[(l + 0) * D4];
            float4 v1 = cb[(l + 1) * D4];
            float4 v2 = cb[(l + 2) * D4];
            float4 v3 = cb[(l + 3) * D4];
            float m0 = sm.s_m[l + 0], m1 = sm.s_m[l + 1];
            float m2 = sm.s_m[l + 2], m3 = sm.s_m[l + 3];
            ms += (m0 + m1) + (m2 + m3);
            a0.x += m0*v0.x; a0.y += m0*v0.y; a0.z += m0*v0.z; a0.w += m0*v0.w;
            a1.x += m1*v1.x; a1.y += m1*v1.y; a1.z += m1*v1.z; a1.w += m1*v1.w;
            a2.x += m2*v2.x; a2.y += m2*v2.y; a2.z += m2*v2.z; a2.w += m2*v2.w;
            a3.x += m3*v3.x; a3.y += m3*v3.y; a3.z += m3*v3.z; a3.w += m3*v3.w;
        }
        float minv = 1.f / fmaxf(ms, 1.f);
        float4 r;
        r.x = ((a0.x + a1.x) + (a2.x + a3.x)) * minv;
        r.y = ((a0.y + a1.y) + (a2.y + a3.y)) * minv;
        r.z = ((a0.z + a1.z) + (a2.z + a3.z)) * minv;
        r.w = ((a0.w + a1.w) + (a2.w + a3.w)) * minv;
        *reinterpret_cast<float4*>(out_mean + (size_t)bs * EMB_D + 4 * ctid) = r;
    } else {
        // ======== SPARSE WARPS: build list (overlapped), then padded walk ==
        const int stid = tid - 192;            // 0..191
        const int ctid = stid;

        // Build 2a: match weights + per-p counts (16 iterations)
        for (int task = stid; task < NP * L_TOK; task += 192) {
            int p = task >> 7;
            int l = task & (L_TOK - 1);
            int sid = sm.s_ids[l];
            int w = 0;
            #pragma unroll
            for (int t = 0; t < NTOK; t++) {
                int aid = sm.s_arg[p * NTOK + t];
                w += (aid != 0 && aid == sid) ? 1 : 0;
            }
            sm.wtab[task] = (unsigned char)w;
            if (w) {
                atomicAdd(&sm.cnt[p], 1);
                atomicAdd(&sm.s_tot[p], w);
            }
        }
        BAR_SPARSE();

        // Build 2b: exclusive scan (1 thread, 24 elems) + padded total
        if (stid == 0) {
            int run = 0;
            #pragma unroll
            for (int p = 0; p < NP; p++) { sm.offs[p] = run; run += sm.cnt[p]; }
            sm.offs[NP] = run;
            sm.total_pad = (run + 7) & ~7;
        }
        BAR_SPARSE();
        if (stid < NP) {
            sm.cursor[stid] = sm.offs[stid];
            int tot = sm.s_tot[stid];
            sm.s_inv[stid] = (tot > 0) ? (1.f / (float)tot) : 0.f;
        }
        // Pad flat list with sentinels (l=0, w=0, p=NP) so the walk needs
        // no per-element bounds checks.
        if (stid < 8) sm.flat[sm.offs[NP] + stid] = (unsigned short)(NP << 11);
        BAR_SPARSE();

        // Build 2c: place events into p-sorted flat list
        for (int task = stid; task < NP * L_TOK; task += 192) {
            int w = sm.wtab[task];
            if (w) {
                int p = task >> 7;
                int l = task & (L_TOK - 1);
                int pos = atomicAdd(&sm.cursor[p], 1);
                sm.flat[pos] = (unsigned short)(l | (w << 7) | (p << 11));
            }
        }
        BAR_SPARSE();

        // Walk: p-sorted register walk, float4, no bounds predication.
        const float4* cb = reinterpret_cast<const float4*>(
                               emb + (size_t)bs * L_TOK * EMB_D) + ctid;
        const int ocol = 4 * ctid;

        const int total_pad = sm.total_pad;
        float4 acc = {0,0,0,0};
        int curp = 0;

        for (int j0 = 0; j0 < total_pad; j0 += 8) {
            float4 vals[8];
            int    es[8];
            #pragma unroll
            for (int k = 0; k < 8; k++) {
                int e = (int)sm.flat[j0 + k];
                es[k] = e;
                // sentinel (p==NP) w=0: load row 0 harmlessly
                vals[k] = cb[(e & 127) * D4];
            }
            #pragma unroll
            for (int k = 0; k < 8; k++) {
                int p = es[k] >> 11;
                if (p != curp) {                       // uniform across half
                    for (int q = curp; q < p && q < NP; q++) {
                        float s = (q == curp) ? sm.s_inv[q] : 0.f;
                        float4 r;
                        r.x = acc.x * s; r.y = acc.y * s;
                        r.z = acc.z * s; r.w = acc.w * s;
                        int set = q >> 3, a = q & 7;
                        *reinterpret_cast<float4*>(
                            out_sets + (size_t)set * set_stride
                            + ((size_t)bs * NARG + a) * EMB_D + ocol) = r;
                    }
                    curp = p;
                    acc = make_float4(0.f, 0.f, 0.f, 0.f);
                }
                float w = (float)((es[k] >> 7) & 15);
                acc.x += w * vals[k].x; acc.y += w * vals[k].y;
                acc.z += w * vals[k].z; acc.w += w * vals[k].w;
            }
        }
        // tail: remaining p's (including all-empty case); curp may be NP
        for (int q = curp; q < NP; q++) {
            float s = (q == curp) ? sm.s_inv[q] : 0.f;
            float4 r;
            r.x = acc.x * s; r.y = acc.y * s; r.z = acc.z * s; r.w = acc.w * s;
            int set = q >> 3, a = q & 7;
            *reinterpret_cast<float4*>(
                out_sets + (size_t)set * set_stride
                + ((size_t)bs * NARG + a) * EMB_D + ocol) = r;
        }
    }
}

extern "C" void kernel_launch(void* const* d_in, const int* in_sizes, int n_in,
                              void* d_out, int out_size)
{
    const int*   sent = (const int*)  d_in[0];
    const int*   mask = (const int*)  d_in[1];
    const int*   pred = (const int*)  d_in[2];
    const int*   a0   = (const int*)  d_in[3];
    const int*   a1   = (const int*)  d_in[4];
    const float* emb  = (const float*)d_in[5];
    float*       out  = (float*)      d_out;

    const int BS = in_sizes[0] / L_TOK;   // 256

    slmuse_fused_kernel<<<BS, BDIM>>>(
        sent, mask, pred, a0, a1, emb, out, BS);
}